// round 1
// baseline (speedup 1.0000x reference)
#include <cuda_runtime.h>

#define LAM 0.95f

// Lambda-return reverse scan.
// acc = reward[i] + discount[i] * (LAM*acc + (1-LAM)*value[i+1]),  i = T-2 .. 0
// out[i] = acc.  Parallel across B; sequential (register-carried) across T.
template <int T>
__global__ void lambda_return_kernel(const float4* __restrict__ reward,
                                     const float4* __restrict__ value,
                                     const float4* __restrict__ discount,
                                     float4* __restrict__ out,
                                     int B4)
{
    int b = blockIdx.x * blockDim.x + threadIdx.x;
    if (b >= B4) return;

    // bootstrap = value[T-1]
    float4 acc = value[(T - 1) * B4 + b];

#pragma unroll
    for (int i = T - 2; i >= 0; --i) {
        float4 r  = reward[i * B4 + b];
        float4 d  = discount[i * B4 + b];
        float4 vn = value[(i + 1) * B4 + b];

        acc.x = fmaf(d.x, fmaf(LAM, acc.x, (1.0f - LAM) * vn.x), r.x);
        acc.y = fmaf(d.y, fmaf(LAM, acc.y, (1.0f - LAM) * vn.y), r.y);
        acc.z = fmaf(d.z, fmaf(LAM, acc.z, (1.0f - LAM) * vn.z), r.z);
        acc.w = fmaf(d.w, fmaf(LAM, acc.w, (1.0f - LAM) * vn.w), r.w);

        out[i * B4 + b] = acc;
    }
}

// Generic (runtime-T) fallback, same math.
__global__ void lambda_return_kernel_gen(const float4* __restrict__ reward,
                                         const float4* __restrict__ value,
                                         const float4* __restrict__ discount,
                                         float4* __restrict__ out,
                                         int B4, int T)
{
    int b = blockIdx.x * blockDim.x + threadIdx.x;
    if (b >= B4) return;

    float4 acc = value[(T - 1) * B4 + b];

    for (int i = T - 2; i >= 0; --i) {
        float4 r  = reward[i * B4 + b];
        float4 d  = discount[i * B4 + b];
        float4 vn = value[(i + 1) * B4 + b];

        acc.x = fmaf(d.x, fmaf(LAM, acc.x, (1.0f - LAM) * vn.x), r.x);
        acc.y = fmaf(d.y, fmaf(LAM, acc.y, (1.0f - LAM) * vn.y), r.y);
        acc.z = fmaf(d.z, fmaf(LAM, acc.z, (1.0f - LAM) * vn.z), r.z);
        acc.w = fmaf(d.w, fmaf(LAM, acc.w, (1.0f - LAM) * vn.w), r.w);

        out[i * B4 + b] = acc;
    }
}

extern "C" void kernel_launch(void* const* d_in, const int* in_sizes, int n_in,
                              void* d_out, int out_size)
{
    // Inputs in metadata order: reward [T,B], value [T,B], discount [T,B].
    const float* reward   = (const float*)d_in[0];
    const float* value    = (const float*)d_in[1];
    const float* discount = (const float*)d_in[2];
    float* out = (float*)d_out;

    // total = T*B, out_size = (T-1)*B  =>  B = total - out_size
    const int total = in_sizes[0];
    const int B = total - out_size;
    const int T = total / B;

    const int B4 = B / 4;  // B = 524288, divisible by 4
    const int threads = 256;
    const int blocks = (B4 + threads - 1) / threads;

    if (T == 16) {
        lambda_return_kernel<16><<<blocks, threads>>>(
            (const float4*)reward, (const float4*)value, (const float4*)discount,
            (float4*)out, B4);
    } else {
        lambda_return_kernel_gen<<<blocks, threads>>>(
            (const float4*)reward, (const float4*)value, (const float4*)discount,
            (float4*)out, B4, T);
    }
}

// round 2
// speedup vs baseline: 1.2031x; 1.2031x over previous
#include <cuda_runtime.h>

#define LAM 0.95f

// Lambda-return reverse scan, 4-deep software-pipelined loads, streaming stores.
// acc = reward[i] + discount[i] * (LAM*acc + (1-LAM)*value[i+1]),  i = T-2 .. 0
template <int T>
__global__ void __launch_bounds__(256)
lambda_return_kernel(const float4* __restrict__ reward,
                     const float4* __restrict__ value,
                     const float4* __restrict__ discount,
                     float4* __restrict__ out,
                     int B4)
{
    const int b = blockIdx.x * blockDim.x + threadIdx.x;
    if (b >= B4) return;

    constexpr int S = T - 1;           // number of scan steps (i = S-1 .. 0)
    constexpr int D = 4;               // pipeline depth

    float4 r[D], d[D], v[D];

    // Prologue: load steps i = S-1 .. S-D into slots k = 0 .. D-1.
#pragma unroll
    for (int k = 0; k < D; ++k) {
        const int i = S - 1 - k;
        r[k] = reward[i * B4 + b];
        d[k] = discount[i * B4 + b];
        v[k] = value[(i + 1) * B4 + b];
    }

    // bootstrap = value[T-1], which is exactly step S-1's v_next (slot 0).
    float4 acc = v[0];

#pragma unroll
    for (int i = S - 1; i >= 0; --i) {
        const int k = (S - 1 - i) % D;
        const float4 rr = r[k];
        const float4 dd = d[k];
        const float4 vv = v[k];

        // Refill this slot with step i-D (issued before the FMAs so the
        // load latency overlaps the arithmetic of the next D steps).
        if (i - D >= 0) {
            const int j = i - D;
            r[k] = reward[j * B4 + b];
            d[k] = discount[j * B4 + b];
            v[k] = value[(j + 1) * B4 + b];
        }

        acc.x = fmaf(dd.x, fmaf(LAM, acc.x, (1.0f - LAM) * vv.x), rr.x);
        acc.y = fmaf(dd.y, fmaf(LAM, acc.y, (1.0f - LAM) * vv.y), rr.y);
        acc.z = fmaf(dd.z, fmaf(LAM, acc.z, (1.0f - LAM) * vv.z), rr.z);
        acc.w = fmaf(dd.w, fmaf(LAM, acc.w, (1.0f - LAM) * vv.w), rr.w);

        // Streaming store: outputs are never re-read; evict-first keeps the
        // input arrays resident in L2 across graph replays.
        __stcs(&out[i * B4 + b], acc);
    }
}

// Generic runtime-T fallback (same math, no unroll tricks).
__global__ void lambda_return_kernel_gen(const float4* __restrict__ reward,
                                         const float4* __restrict__ value,
                                         const float4* __restrict__ discount,
                                         float4* __restrict__ out,
                                         int B4, int T)
{
    const int b = blockIdx.x * blockDim.x + threadIdx.x;
    if (b >= B4) return;

    float4 acc = value[(T - 1) * B4 + b];

    for (int i = T - 2; i >= 0; --i) {
        float4 r  = reward[i * B4 + b];
        float4 d  = discount[i * B4 + b];
        float4 vn = value[(i + 1) * B4 + b];

        acc.x = fmaf(d.x, fmaf(LAM, acc.x, (1.0f - LAM) * vn.x), r.x);
        acc.y = fmaf(d.y, fmaf(LAM, acc.y, (1.0f - LAM) * vn.y), r.y);
        acc.z = fmaf(d.z, fmaf(LAM, acc.z, (1.0f - LAM) * vn.z), r.z);
        acc.w = fmaf(d.w, fmaf(LAM, acc.w, (1.0f - LAM) * vn.w), r.w);

        __stcs(&out[i * B4 + b], acc);
    }
}

extern "C" void kernel_launch(void* const* d_in, const int* in_sizes, int n_in,
                              void* d_out, int out_size)
{
    // Inputs in metadata order: reward [T,B], value [T,B], discount [T,B].
    const float* reward   = (const float*)d_in[0];
    const float* value    = (const float*)d_in[1];
    const float* discount = (const float*)d_in[2];
    float* out = (float*)d_out;

    // total = T*B, out_size = (T-1)*B  =>  B = total - out_size
    const int total = in_sizes[0];
    const int B = total - out_size;
    const int T = total / B;

    const int B4 = B / 4;  // B = 524288, divisible by 4
    const int threads = 256;
    const int blocks = (B4 + threads - 1) / threads;

    if (T == 16) {
        lambda_return_kernel<16><<<blocks, threads>>>(
            (const float4*)reward, (const float4*)value, (const float4*)discount,
            (float4*)out, B4);
    } else {
        lambda_return_kernel_gen<<<blocks, threads>>>(
            (const float4*)reward, (const float4*)value, (const float4*)discount,
            (float4*)out, B4, T);
    }
}